// round 2
// baseline (speedup 1.0000x reference)
#include <cuda_runtime.h>
#include <cstdint>

#define N_NODES 50000
#define N_EDGES 1600000
#define N_GRAPHS 2048
#define D 133
#define DP 136          // padded row length (34 float4)
#define EPSV 1e-5f
#define GR 8            // rows per warp in GEMM

// -------- scratch (static device globals; no runtime allocation) --------
__device__ __align__(16) float g_A[(size_t)N_NODES * DP];   // gather source (g = dinv*h)
__device__ __align__(16) float g_B[(size_t)N_NODES * DP];   // accumulator
__device__ __align__(16) float g_C[(size_t)N_NODES * DP];   // layer-2 input
__device__ float g_deg[N_NODES];
__device__ float g_dinv[N_NODES];

// ------------------------------------------------------------------
__global__ void init_deg_kernel() {
    int i = blockIdx.x * blockDim.x + threadIdx.x;
    if (i < N_NODES) g_deg[i] = 1.0f;   // self-loop
}

__global__ void count_deg_kernel(const int* __restrict__ ei) {
    int e = blockIdx.x * blockDim.x + threadIdx.x;
    if (e < N_EDGES) {
        int c = __ldg(&ei[N_EDGES + e]);   // col
        atomicAdd(&g_deg[c], 1.0f);
    }
}

__global__ void dinv_kernel() {
    int i = blockIdx.x * blockDim.x + threadIdx.x;
    if (i < N_NODES) g_dinv[i] = rsqrtf(g_deg[i]);
}

// ------------------------------------------------------------------
// GEMM: H = X @ W ; then g = dinv[row] * H written to BOTH g_A and g_B.
// W lives in SMEM [133][136]; each warp register-blocks GR=8 rows x 5 col-chunks.
__global__ void gemm_scale_kernel(const float* __restrict__ X, int ldx,
                                  const float* __restrict__ W) {
    extern __shared__ float sm[];
    float* ws = sm;                 // [D][DP]
    float* xs = sm + D * DP;        // [8 warps][GR][DP]

    int tid  = threadIdx.x;
    int w    = tid >> 5;
    int lane = tid & 31;

    for (int i = tid; i < D * D; i += blockDim.x)
        ws[(i / D) * DP + (i % D)] = W[i];
    __syncthreads();

    int rowbase = (blockIdx.x * 8 + w) * GR;
    float* xw = xs + w * GR * DP;

    // stage this warp's GR input rows into smem
    for (int r = 0; r < GR; r++) {
        int row = rowbase + r;
        for (int c = lane; c < DP; c += 32)
            xw[r * DP + c] = (row < N_NODES && c < D) ? X[(size_t)row * ldx + c] : 0.0f;
    }
    __syncwarp();

    float acc[GR][5];
#pragma unroll
    for (int r = 0; r < GR; r++)
#pragma unroll
        for (int j = 0; j < 5; j++) acc[r][j] = 0.0f;

    for (int k = 0; k < D; k++) {
        float wv[5];
#pragma unroll
        for (int j = 0; j < 4; j++) wv[j] = ws[k * DP + lane + 32 * j];
        wv[4] = (lane < D - 128) ? ws[k * DP + lane + 128] : 0.0f;
#pragma unroll
        for (int r = 0; r < GR; r++) {
            float xv = xw[r * DP + k];   // LDS broadcast
#pragma unroll
            for (int j = 0; j < 5; j++) acc[r][j] = fmaf(xv, wv[j], acc[r][j]);
        }
    }

#pragma unroll
    for (int r = 0; r < GR; r++) {
        int row = rowbase + r;
        if (row >= N_NODES) break;
        float dv = g_dinv[row];
        size_t base = (size_t)row * DP;
#pragma unroll
        for (int j = 0; j < 5; j++) {
            int c = lane + 32 * j;
            if (c < D) {
                float v = dv * acc[r][j];
                g_A[base + c] = v;
                g_B[base + c] = v;      // accumulator starts at g (self-loop term)
            } else if (c < DP) {
                g_A[base + c] = 0.0f;
                g_B[base + c] = 0.0f;
            }
        }
    }
}

// ------------------------------------------------------------------
// Edge scatter: B[col] += A[row]. Flat (edge, float4-chunk) decomposition,
// fully coalesced 544B/row; vector red to keep LSU issue below L2 cap.
__global__ void scatter_kernel(const int* __restrict__ ei) {
    int idx = blockIdx.x * blockDim.x + threadIdx.x;
    if (idx >= N_EDGES * 34) return;
    int e = idx / 34;
    int c = idx - e * 34;
    int r  = __ldg(&ei[e]);
    int cl = __ldg(&ei[N_EDGES + e]);
    const float4 v = *((const float4*)(g_A + (size_t)r * DP) + c);
    float* dst = g_B + (size_t)cl * DP + c * 4;
    unsigned long long gp = (unsigned long long)__cvta_generic_to_global(dst);
    asm volatile("red.global.add.v4.f32 [%0], {%1,%2,%3,%4};"
                 :: "l"(gp), "f"(v.x), "f"(v.y), "f"(v.z), "f"(v.w)
                 : "memory");
}

// ------------------------------------------------------------------
// post: out = BN(relu(dinv*acc + bias)); pads written 0.
__global__ void post_kernel(const float* __restrict__ acc, float* __restrict__ out,
                            const float* __restrict__ bias, const float* __restrict__ gamma,
                            const float* __restrict__ beta, const float* __restrict__ rm,
                            const float* __restrict__ rv) {
    int idx = blockIdx.x * blockDim.x + threadIdx.x;
    if (idx >= N_NODES * DP) return;
    int c = idx % DP;
    int n = idx / DP;
    float v = 0.0f;
    if (c < D) {
        v = g_dinv[n] * acc[idx] + __ldg(&bias[c]);
        v = fmaxf(v, 0.0f);
        v = (v - __ldg(&rm[c])) * rsqrtf(__ldg(&rv[c]) + EPSV) * __ldg(&gamma[c])
            + __ldg(&beta[c]);
    }
    out[idx] = v;
}

// ------------------------------------------------------------------
__device__ __forceinline__ int lbound(const int* b, int n, int v) {
    int lo = 0, hi = n;
    while (lo < hi) { int m = (lo + hi) >> 1; if (b[m] < v) lo = m + 1; else hi = m; }
    return lo;
}

// mean-pool per graph; batch is sorted -> binary search for segment, no atomics.
__global__ void pool_kernel(const float* __restrict__ H,
                            const int* __restrict__ batch,
                            float* __restrict__ out) {
    __shared__ int s_lo, s_hi;
    int g = blockIdx.x;
    if (threadIdx.x == 0) s_lo = lbound(batch, N_NODES, g);
    if (threadIdx.x == 1) s_hi = lbound(batch, N_NODES, g + 1);
    __syncthreads();
    int lo = s_lo, hi = s_hi;
    int c = threadIdx.x;
    if (c < D) {
        float s = 0.0f;
        for (int n = lo; n < hi; n++) s += H[(size_t)n * DP + c];
        float cnt = (float)(hi - lo);
        out[g * D + c] = s / fmaxf(cnt, 1.0f);
    }
}

// ------------------------------------------------------------------
extern "C" void kernel_launch(void* const* d_in, const int* in_sizes, int n_in,
                              void* d_out, int out_size) {
    const float* x     = (const float*)d_in[0];
    const int*   ei    = (const int*)d_in[1];
    const int*   batch = (const int*)d_in[2];
    const float* W1  = (const float*)d_in[3];
    const float* b1  = (const float*)d_in[4];
    const float* W2  = (const float*)d_in[5];
    const float* b2  = (const float*)d_in[6];
    const float* g1  = (const float*)d_in[7];
    const float* be1 = (const float*)d_in[8];
    const float* rm1 = (const float*)d_in[9];
    const float* rv1 = (const float*)d_in[10];
    const float* g2  = (const float*)d_in[11];
    const float* be2 = (const float*)d_in[12];
    const float* rm2 = (const float*)d_in[13];
    const float* rv2 = (const float*)d_in[14];
    float* out = (float*)d_out;

    float *pA, *pB, *pC;
    cudaGetSymbolAddress((void**)&pA, g_A);
    cudaGetSymbolAddress((void**)&pB, g_B);
    cudaGetSymbolAddress((void**)&pC, g_C);

    const int smem = (D * DP + 8 * GR * DP) * (int)sizeof(float);  // ~107 KB
    cudaFuncSetAttribute((const void*)gemm_scale_kernel,
                         cudaFuncAttributeMaxDynamicSharedMemorySize, smem);

    const int TB = 256;
    init_deg_kernel<<<(N_NODES + TB - 1) / TB, TB>>>();
    count_deg_kernel<<<(N_EDGES + TB - 1) / TB, TB>>>(ei);
    dinv_kernel<<<(N_NODES + TB - 1) / TB, TB>>>();

    const int gemm_blocks = (N_NODES + 8 * GR - 1) / (8 * GR);
    const int scat_total  = N_EDGES * 34;                       // 54.4M, fits int
    const int scat_blocks = (scat_total + TB - 1) / TB;
    const int post_total  = N_NODES * DP;
    const int post_blocks = (post_total + TB - 1) / TB;

    // ---- layer 1 ----
    gemm_scale_kernel<<<gemm_blocks, TB, smem>>>(x, D, W1);
    scatter_kernel<<<scat_blocks, TB>>>(ei);
    post_kernel<<<post_blocks, TB>>>(pB, pC, b1, g1, be1, rm1, rv1);

    // ---- layer 2 ----
    gemm_scale_kernel<<<gemm_blocks, TB, smem>>>(pC, DP, W2);
    scatter_kernel<<<scat_blocks, TB>>>(ei);
    post_kernel<<<post_blocks, TB>>>(pB, pA, b2, g2, be2, rm2, rv2);

    // ---- per-graph mean pool ----
    pool_kernel<<<N_GRAPHS, 160>>>(pA, batch, out);
}

// round 3
// speedup vs baseline: 2.3882x; 2.3882x over previous
#include <cuda_runtime.h>
#include <cstdint>

#define N_NODES 50000
#define N_EDGES 1600000
#define N_GRAPHS 2048
#define D 133
#define DP 136          // padded row length (34 float4)
#define EPSV 1e-5f
#define GR 8            // rows per warp in GEMM
#define SCAN_B 1024
#define SCAN_NB ((N_NODES + SCAN_B - 1) / SCAN_B)   // 49

// -------- scratch (static device globals; no runtime allocation) --------
__device__ __align__(16) float g_A[(size_t)N_NODES * DP];   // gemm output (dinv-scaled)
__device__ __align__(16) float g_C[(size_t)N_NODES * DP];   // gather output / layer-2 input
__device__ __align__(16) float g_P[(size_t)N_GRAPHS * DP];  // pool accumulator
__device__ float g_dinv[N_NODES];
__device__ int   g_cnt[N_NODES];
__device__ int   g_off[N_NODES + 1];
__device__ int   g_cursor[N_NODES];
__device__ int   g_csr[N_EDGES];
__device__ int   g_bsum[SCAN_NB];
__device__ int   g_cntg[N_GRAPHS];
__device__ float g_post1[3 * DP];    // bias | s | t   (padded)
__device__ float g_post2[3 * DP];

// ------------------------------------------------------------------
__global__ void zero_cnt_kernel() {
    int i = blockIdx.x * blockDim.x + threadIdx.x;
    if (i < N_NODES) g_cnt[i] = 0;
}

__global__ void zero_pool_kernel() {
    int i = blockIdx.x * blockDim.x + threadIdx.x;
    if (i < N_GRAPHS * DP) g_P[i] = 0.0f;
}

__global__ void count_deg_kernel(const int* __restrict__ ei) {
    int e = blockIdx.x * blockDim.x + threadIdx.x;
    if (e < N_EDGES) atomicAdd(&g_cnt[__ldg(&ei[N_EDGES + e])], 1);
}

__global__ void dinv_kernel() {
    int i = blockIdx.x * blockDim.x + threadIdx.x;
    if (i < N_NODES) g_dinv[i] = rsqrtf((float)(g_cnt[i] + 1));   // +1 self-loop
}

// ---- 3-kernel exclusive scan of g_cnt -> g_off ----
__global__ void scan1_kernel() {
    __shared__ int sh[SCAN_B];
    int t = threadIdx.x;
    int i = blockIdx.x * SCAN_B + t;
    int v = (i < N_NODES) ? g_cnt[i] : 0;
    sh[t] = v;
    __syncthreads();
#pragma unroll
    for (int d = 1; d < SCAN_B; d <<= 1) {
        int x = (t >= d) ? sh[t - d] : 0;
        __syncthreads();
        sh[t] += x;
        __syncthreads();
    }
    if (i < N_NODES) g_off[i] = sh[t] - v;           // exclusive, local
    if (t == SCAN_B - 1) g_bsum[blockIdx.x] = sh[t];
}

__global__ void scan2_kernel() {
    if (threadIdx.x == 0) {
        int acc = 0;
        for (int b = 0; b < SCAN_NB; b++) {
            int v = g_bsum[b];
            g_bsum[b] = acc;
            acc += v;
        }
    }
}

__global__ void scan3_kernel() {
    int i = blockIdx.x * blockDim.x + threadIdx.x;
    if (i < N_NODES) {
        int o = g_off[i] + g_bsum[i / SCAN_B];
        g_off[i] = o;
        g_cursor[i] = o;
    }
    if (i == 0) g_off[N_NODES] = N_EDGES;
}

__global__ void fill_csr_kernel(const int* __restrict__ ei) {
    int e = blockIdx.x * blockDim.x + threadIdx.x;
    if (e < N_EDGES) {
        int r = __ldg(&ei[e]);
        int c = __ldg(&ei[N_EDGES + e]);
        int pos = atomicAdd(&g_cursor[c], 1);
        g_csr[pos] = r;
    }
}

// ---- per-layer fused BN constants: bias | s | t, zero-padded to DP ----
__global__ void prep_post_kernel(const float* __restrict__ bias, const float* __restrict__ gam,
                                 const float* __restrict__ beta, const float* __restrict__ rm,
                                 const float* __restrict__ rv, float* __restrict__ dst) {
    int c = threadIdx.x;
    if (c >= DP) return;
    float bb = 0.0f, ss = 0.0f, tt = 0.0f;
    if (c < D) {
        bb = bias[c];
        float sc = gam[c] * rsqrtf(rv[c] + EPSV);
        ss = sc;
        tt = beta[c] - rm[c] * sc;
    }
    dst[c] = bb; dst[DP + c] = ss; dst[2 * DP + c] = tt;
}

// ------------------------------------------------------------------
// GEMM: out = dinv[row] * (X @ W) written to g_A (pads zeroed).
// W in smem [D][DP]; warp register-blocks GR rows x 5 col-chunks; k-unroll 4.
__global__ __launch_bounds__(256, 2)
void gemm_scale_kernel(const float* __restrict__ X, int ldx,
                       const float* __restrict__ W) {
    extern __shared__ float sm[];
    float* ws = sm;                 // [D][DP]
    float* xs = sm + D * DP;        // [8 warps][GR][DP]

    int tid  = threadIdx.x;
    int w    = tid >> 5;
    int lane = tid & 31;

    for (int i = tid; i < D * D; i += blockDim.x)
        ws[(i / D) * DP + (i % D)] = W[i];
    __syncthreads();

    int rowbase = (blockIdx.x * 8 + w) * GR;
    float* xw = xs + w * GR * DP;

    for (int r = 0; r < GR; r++) {
        int row = rowbase + r;
        for (int c = lane; c < DP; c += 32)
            xw[r * DP + c] = (row < N_NODES && c < D) ? X[(size_t)row * ldx + c] : 0.0f;
    }
    __syncwarp();

    float acc[GR][5];
#pragma unroll
    for (int r = 0; r < GR; r++)
#pragma unroll
        for (int j = 0; j < 5; j++) acc[r][j] = 0.0f;

    // main: k in chunks of 4 (132 = 33*4), tail k=132
    for (int k = 0; k < D - 1; k += 4) {
        float wv[4][5];
#pragma unroll
        for (int kk = 0; kk < 4; kk++) {
#pragma unroll
            for (int j = 0; j < 4; j++) wv[kk][j] = ws[(k + kk) * DP + lane + 32 * j];
            wv[kk][4] = (lane < D - 128) ? ws[(k + kk) * DP + 128 + lane] : 0.0f;
        }
#pragma unroll
        for (int r = 0; r < GR; r++) {
            float4 xv = *(const float4*)&xw[r * DP + k];
#pragma unroll
            for (int j = 0; j < 5; j++) {
                acc[r][j] = fmaf(xv.x, wv[0][j], acc[r][j]);
                acc[r][j] = fmaf(xv.y, wv[1][j], acc[r][j]);
                acc[r][j] = fmaf(xv.z, wv[2][j], acc[r][j]);
                acc[r][j] = fmaf(xv.w, wv[3][j], acc[r][j]);
            }
        }
    }
    {   // tail k = 132
        const int k = D - 1;
        float wv[5];
#pragma unroll
        for (int j = 0; j < 4; j++) wv[j] = ws[k * DP + lane + 32 * j];
        wv[4] = (lane < D - 128) ? ws[k * DP + 128 + lane] : 0.0f;
#pragma unroll
        for (int r = 0; r < GR; r++) {
            float xv = xw[r * DP + k];
#pragma unroll
            for (int j = 0; j < 5; j++) acc[r][j] = fmaf(xv, wv[j], acc[r][j]);
        }
    }

#pragma unroll
    for (int r = 0; r < GR; r++) {
        int row = rowbase + r;
        if (row >= N_NODES) break;
        float dv = g_dinv[row];
        size_t base = (size_t)row * DP;
#pragma unroll
        for (int j = 0; j < 5; j++) {
            int c = lane + 32 * j;
            if (c < D)       g_A[base + c] = dv * acc[r][j];
            else if (c < DP) g_A[base + c] = 0.0f;
        }
    }
}

// ------------------------------------------------------------------
// Warp-per-node CSR gather + fused epilogue.
// acc = A[n] + sum_{e in in(n)} A[src(e)];  v = relu(dinv[n]*acc + bias)*s + t
// do_pool==0: write v row to Cout.  do_pool==1: red.v4 v into g_P[batch[n]].
__global__ __launch_bounds__(256)
void gather_post_kernel(const float* __restrict__ A, float* __restrict__ Cout,
                        const float* __restrict__ post, int do_pool,
                        const int* __restrict__ batch) {
    int gw = (blockIdx.x * blockDim.x + threadIdx.x) >> 5;
    if (gw >= N_NODES) return;
    int lane = threadIdx.x & 31;
    int n = gw;

    int lo = __ldg(&g_off[n]);
    int hi = __ldg(&g_off[n + 1]);

    const float4* An = (const float4*)(A + (size_t)n * DP);
    float4 a0 = __ldg(An + lane);
    float4 a1 = make_float4(0.f, 0.f, 0.f, 0.f);
    if (lane < 2) a1 = __ldg(An + lane + 32);

    int e = lo;
    for (; e + 32 <= hi; e += 32) {
        int src = __ldg(&g_csr[e + lane]);
#pragma unroll 4
        for (int j = 0; j < 32; j++) {
            int sj = __shfl_sync(0xffffffffu, src, j);
            const float4* R = (const float4*)(A + (size_t)sj * DP);
            float4 v0 = __ldg(R + lane);
            a0.x += v0.x; a0.y += v0.y; a0.z += v0.z; a0.w += v0.w;
            if (lane < 2) {
                float4 v1 = __ldg(R + lane + 32);
                a1.x += v1.x; a1.y += v1.y; a1.z += v1.z; a1.w += v1.w;
            }
        }
    }
    for (; e < hi; e++) {
        int sj = __ldg(&g_csr[e]);
        const float4* R = (const float4*)(A + (size_t)sj * DP);
        float4 v0 = __ldg(R + lane);
        a0.x += v0.x; a0.y += v0.y; a0.z += v0.z; a0.w += v0.w;
        if (lane < 2) {
            float4 v1 = __ldg(R + lane + 32);
            a1.x += v1.x; a1.y += v1.y; a1.z += v1.z; a1.w += v1.w;
        }
    }

    float dv = __ldg(&g_dinv[n]);
    const float* bb = post;
    const float* ss = post + DP;
    const float* tt = post + 2 * DP;

    int c0 = 4 * lane;
    float4 o0;
    o0.x = fmaf(fmaxf(fmaf(dv, a0.x, __ldg(&bb[c0 + 0])), 0.f), __ldg(&ss[c0 + 0]), __ldg(&tt[c0 + 0]));
    o0.y = fmaf(fmaxf(fmaf(dv, a0.y, __ldg(&bb[c0 + 1])), 0.f), __ldg(&ss[c0 + 1]), __ldg(&tt[c0 + 1]));
    o0.z = fmaf(fmaxf(fmaf(dv, a0.z, __ldg(&bb[c0 + 2])), 0.f), __ldg(&ss[c0 + 2]), __ldg(&tt[c0 + 2]));
    o0.w = fmaf(fmaxf(fmaf(dv, a0.w, __ldg(&bb[c0 + 3])), 0.f), __ldg(&ss[c0 + 3]), __ldg(&tt[c0 + 3]));
    float4 o1 = make_float4(0.f, 0.f, 0.f, 0.f);
    if (lane < 2) {
        int c1 = 128 + 4 * lane;
        o1.x = fmaf(fmaxf(fmaf(dv, a1.x, __ldg(&bb[c1 + 0])), 0.f), __ldg(&ss[c1 + 0]), __ldg(&tt[c1 + 0]));
        o1.y = fmaf(fmaxf(fmaf(dv, a1.y, __ldg(&bb[c1 + 1])), 0.f), __ldg(&ss[c1 + 1]), __ldg(&tt[c1 + 1]));
        o1.z = fmaf(fmaxf(fmaf(dv, a1.z, __ldg(&bb[c1 + 2])), 0.f), __ldg(&ss[c1 + 2]), __ldg(&tt[c1 + 2]));
        o1.w = fmaf(fmaxf(fmaf(dv, a1.w, __ldg(&bb[c1 + 3])), 0.f), __ldg(&ss[c1 + 3]), __ldg(&tt[c1 + 3]));
    }

    if (!do_pool) {
        float4* Cn = (float4*)(Cout + (size_t)n * DP);
        Cn[lane] = o0;
        if (lane < 2) Cn[lane + 32] = o1;
    } else {
        int g = __ldg(&batch[n]);
        float* dst0 = g_P + (size_t)g * DP + 4 * lane;
        unsigned long long p0 = (unsigned long long)__cvta_generic_to_global(dst0);
        asm volatile("red.global.add.v4.f32 [%0], {%1,%2,%3,%4};"
                     :: "l"(p0), "f"(o0.x), "f"(o0.y), "f"(o0.z), "f"(o0.w) : "memory");
        if (lane < 2) {
            float* dst1 = g_P + (size_t)g * DP + 128 + 4 * lane;
            unsigned long long p1 = (unsigned long long)__cvta_generic_to_global(dst1);
            asm volatile("red.global.add.v4.f32 [%0], {%1,%2,%3,%4};"
                         :: "l"(p1), "f"(o1.x), "f"(o1.y), "f"(o1.z), "f"(o1.w) : "memory");
        }
    }
}

// ------------------------------------------------------------------
__device__ __forceinline__ int lbound(const int* b, int n, int v) {
    int lo = 0, hi = n;
    while (lo < hi) { int m = (lo + hi) >> 1; if (b[m] < v) lo = m + 1; else hi = m; }
    return lo;
}

__global__ void cntg_kernel(const int* __restrict__ batch) {
    int g = blockIdx.x * blockDim.x + threadIdx.x;
    if (g < N_GRAPHS)
        g_cntg[g] = lbound(batch, N_NODES, g + 1) - lbound(batch, N_NODES, g);
}

__global__ void divide_kernel(float* __restrict__ out) {
    int idx = blockIdx.x * blockDim.x + threadIdx.x;
    if (idx >= N_GRAPHS * D) return;
    int g = idx / D;
    int c = idx - g * D;
    float cnt = (float)g_cntg[g];
    out[idx] = g_P[(size_t)g * DP + c] / fmaxf(cnt, 1.0f);
}

// ------------------------------------------------------------------
extern "C" void kernel_launch(void* const* d_in, const int* in_sizes, int n_in,
                              void* d_out, int out_size) {
    const float* x     = (const float*)d_in[0];
    const int*   ei    = (const int*)d_in[1];
    const int*   batch = (const int*)d_in[2];
    const float* W1  = (const float*)d_in[3];
    const float* b1  = (const float*)d_in[4];
    const float* W2  = (const float*)d_in[5];
    const float* b2  = (const float*)d_in[6];
    const float* g1  = (const float*)d_in[7];
    const float* be1 = (const float*)d_in[8];
    const float* rm1 = (const float*)d_in[9];
    const float* rv1 = (const float*)d_in[10];
    const float* g2  = (const float*)d_in[11];
    const float* be2 = (const float*)d_in[12];
    const float* rm2 = (const float*)d_in[13];
    const float* rv2 = (const float*)d_in[14];
    float* out = (float*)d_out;

    float *pA, *pC, *pP1, *pP2;
    cudaGetSymbolAddress((void**)&pA, g_A);
    cudaGetSymbolAddress((void**)&pC, g_C);
    cudaGetSymbolAddress((void**)&pP1, g_post1);
    cudaGetSymbolAddress((void**)&pP2, g_post2);

    const int smem = (D * DP + 8 * GR * DP) * (int)sizeof(float);  // ~107 KB
    cudaFuncSetAttribute((const void*)gemm_scale_kernel,
                         cudaFuncAttributeMaxDynamicSharedMemorySize, smem);

    const int TB = 256;
    // ---- graph preprocessing (CSR + dinv) ----
    zero_cnt_kernel<<<(N_NODES + TB - 1) / TB, TB>>>();
    zero_pool_kernel<<<(N_GRAPHS * DP + TB - 1) / TB, TB>>>();
    count_deg_kernel<<<(N_EDGES + TB - 1) / TB, TB>>>(ei);
    dinv_kernel<<<(N_NODES + TB - 1) / TB, TB>>>();
    scan1_kernel<<<SCAN_NB, SCAN_B>>>();
    scan2_kernel<<<1, 32>>>();
    scan3_kernel<<<SCAN_NB, SCAN_B>>>();
    fill_csr_kernel<<<(N_EDGES + TB - 1) / TB, TB>>>(ei);
    prep_post_kernel<<<1, DP>>>(b1, g1, be1, rm1, rv1, pP1);
    prep_post_kernel<<<1, DP>>>(b2, g2, be2, rm2, rv2, pP2);

    const int gemm_blocks   = (N_NODES + 8 * GR - 1) / (8 * GR);
    const int gather_blocks = (N_NODES * 32 + TB - 1) / TB;   // warp per node

    // ---- layer 1 ----
    gemm_scale_kernel<<<gemm_blocks, TB, smem>>>(x, D, W1);
    gather_post_kernel<<<gather_blocks, TB>>>(pA, pC, pP1, 0, batch);

    // ---- layer 2 (+ fused pool accumulate) ----
    gemm_scale_kernel<<<gemm_blocks, TB, smem>>>(pC, DP, W2);
    gather_post_kernel<<<gather_blocks, TB>>>(pA, pC, pP2, 1, batch);

    // ---- per-graph mean ----
    cntg_kernel<<<(N_GRAPHS + TB - 1) / TB, TB>>>(batch);
    divide_kernel<<<(N_GRAPHS * D + TB - 1) / TB, TB>>>(out);
}

// round 4
// speedup vs baseline: 2.6235x; 1.0985x over previous
#include <cuda_runtime.h>
#include <cuda_fp16.h>
#include <cstdint>

#define N_NODES 50000
#define N_EDGES 1600000
#define N_GRAPHS 2048
#define D 133
#define DP 136           // fp32 padded row (floats)
#define DPH 144          // fp16 padded row (halves) = 288B = 9 sectors, 16B-aligned
#define EPSV 1e-5f
#define GR 8             // rows per warp in GEMM
#define GEMM_T 512       // threads per GEMM block (16 warps)
#define SCAN_B 1024
#define SCAN_NB ((N_NODES + SCAN_B - 1) / SCAN_B)   // 49

// -------- scratch (static device globals; no runtime allocation) --------
__device__ __align__(16) __half g_A16[(size_t)N_NODES * DPH];  // gemm out, dinv-scaled, fp16
__device__ __align__(16) float  g_C[(size_t)N_NODES * DP];     // gather out / layer-2 input
__device__ __align__(16) float  g_P[(size_t)N_GRAPHS * DP];    // pool accumulator
__device__ float g_dinv[N_NODES];
__device__ int   g_cnt[N_NODES];
__device__ int   g_off[N_NODES + 1];
__device__ int   g_cursor[N_NODES];
__device__ int   g_csr[N_EDGES];
__device__ int   g_bsum[SCAN_NB];
__device__ int   g_cntg[N_GRAPHS];
__device__ float g_post1[3 * DP];    // bias | s | t   (zero-padded)
__device__ float g_post2[3 * DP];

// ------------------------------------------------------------------
__global__ void zero_cnt_kernel() {
    int i = blockIdx.x * blockDim.x + threadIdx.x;
    if (i < N_NODES) g_cnt[i] = 0;
}

__global__ void zero_pool_kernel() {
    int i = blockIdx.x * blockDim.x + threadIdx.x;
    if (i < N_GRAPHS * DP) g_P[i] = 0.0f;
}

__global__ void count_deg_kernel(const int* __restrict__ ei) {
    int e = blockIdx.x * blockDim.x + threadIdx.x;
    if (e < N_EDGES) atomicAdd(&g_cnt[__ldg(&ei[N_EDGES + e])], 1);
}

__global__ void dinv_kernel() {
    int i = blockIdx.x * blockDim.x + threadIdx.x;
    if (i < N_NODES) g_dinv[i] = rsqrtf((float)(g_cnt[i] + 1));   // +1 self-loop
}

// ---- 3-kernel exclusive scan of g_cnt -> g_off ----
__global__ void scan1_kernel() {
    __shared__ int sh[SCAN_B];
    int t = threadIdx.x;
    int i = blockIdx.x * SCAN_B + t;
    int v = (i < N_NODES) ? g_cnt[i] : 0;
    sh[t] = v;
    __syncthreads();
#pragma unroll
    for (int d = 1; d < SCAN_B; d <<= 1) {
        int x = (t >= d) ? sh[t - d] : 0;
        __syncthreads();
        sh[t] += x;
        __syncthreads();
    }
    if (i < N_NODES) g_off[i] = sh[t] - v;           // exclusive, local
    if (t == SCAN_B - 1) g_bsum[blockIdx.x] = sh[t];
}

__global__ void scan2_kernel() {
    if (threadIdx.x == 0) {
        int acc = 0;
        for (int b = 0; b < SCAN_NB; b++) {
            int v = g_bsum[b];
            g_bsum[b] = acc;
            acc += v;
        }
    }
}

__global__ void scan3_kernel() {
    int i = blockIdx.x * blockDim.x + threadIdx.x;
    if (i < N_NODES) {
        int o = g_off[i] + g_bsum[i / SCAN_B];
        g_off[i] = o;
        g_cursor[i] = o;
    }
    if (i == 0) g_off[N_NODES] = N_EDGES;
}

__global__ void fill_csr_kernel(const int* __restrict__ ei) {
    int e = blockIdx.x * blockDim.x + threadIdx.x;
    if (e < N_EDGES) {
        int r = __ldg(&ei[e]);
        int c = __ldg(&ei[N_EDGES + e]);
        int pos = atomicAdd(&g_cursor[c], 1);
        g_csr[pos] = r;
    }
}

// ---- per-layer fused BN constants: bias | s | t, zero-padded to DP ----
__global__ void prep_post_kernel(const float* __restrict__ bias, const float* __restrict__ gam,
                                 const float* __restrict__ beta, const float* __restrict__ rm,
                                 const float* __restrict__ rv, float* __restrict__ dst) {
    int c = threadIdx.x;
    if (c >= DP) return;
    float bb = 0.0f, ss = 0.0f, tt = 0.0f;
    if (c < D) {
        bb = bias[c];
        float sc = gam[c] * rsqrtf(rv[c] + EPSV);
        ss = sc;
        tt = beta[c] - rm[c] * sc;
    }
    dst[c] = bb; dst[DP + c] = ss; dst[2 * DP + c] = tt;
}

// ------------------------------------------------------------------
// GEMM: g_A16[row] = fp16( dinv[row] * (X @ W) ), pads zeroed.
// W in smem [D][DP]; 16 warps x GR=8 rows; k-unroll 4 with float4 broadcasts.
__global__ __launch_bounds__(GEMM_T, 1)
void gemm_scale_kernel(const float* __restrict__ X, int ldx,
                       const float* __restrict__ W) {
    extern __shared__ float sm[];
    float* ws = sm;                    // [D][DP]   72.4 KB
    float* xs = sm + D * DP;           // [16 warps][GR][DP]  69.6 KB

    int tid  = threadIdx.x;
    int w    = tid >> 5;
    int lane = tid & 31;

    for (int i = tid; i < D * D; i += GEMM_T)
        ws[(i / D) * DP + (i % D)] = W[i];
    __syncthreads();

    int rowbase = (blockIdx.x * 16 + w) * GR;
    float* xw = xs + w * GR * DP;

    for (int r = 0; r < GR; r++) {
        int row = rowbase + r;
        for (int c = lane; c < DP; c += 32)
            xw[r * DP + c] = (row < N_NODES && c < D) ? X[(size_t)row * ldx + c] : 0.0f;
    }
    __syncwarp();

    float acc[GR][5];
#pragma unroll
    for (int r = 0; r < GR; r++)
#pragma unroll
        for (int j = 0; j < 5; j++) acc[r][j] = 0.0f;

    // main: k in chunks of 4 (132 = 33*4), tail k=132
    for (int k = 0; k < D - 1; k += 4) {
        float wv[4][5];
#pragma unroll
        for (int kk = 0; kk < 4; kk++) {
#pragma unroll
            for (int j = 0; j < 4; j++) wv[kk][j] = ws[(k + kk) * DP + lane + 32 * j];
            wv[kk][4] = (lane < D - 128) ? ws[(k + kk) * DP + 128 + lane] : 0.0f;
        }
#pragma unroll
        for (int r = 0; r < GR; r++) {
            float4 xv = *(const float4*)&xw[r * DP + k];
#pragma unroll
            for (int j = 0; j < 5; j++) {
                acc[r][j] = fmaf(xv.x, wv[0][j], acc[r][j]);
                acc[r][j] = fmaf(xv.y, wv[1][j], acc[r][j]);
                acc[r][j] = fmaf(xv.z, wv[2][j], acc[r][j]);
                acc[r][j] = fmaf(xv.w, wv[3][j], acc[r][j]);
            }
        }
    }
    {   // tail k = 132
        const int k = D - 1;
        float wv[5];
#pragma unroll
        for (int j = 0; j < 4; j++) wv[j] = ws[k * DP + lane + 32 * j];
        wv[4] = (lane < D - 128) ? ws[k * DP + 128 + lane] : 0.0f;
#pragma unroll
        for (int r = 0; r < GR; r++) {
            float xv = xw[r * DP + k];
#pragma unroll
            for (int j = 0; j < 5; j++) acc[r][j] = fmaf(xv, wv[j], acc[r][j]);
        }
    }

#pragma unroll
    for (int r = 0; r < GR; r++) {
        int row = rowbase + r;
        if (row >= N_NODES) break;
        float dv = g_dinv[row];
        size_t base = (size_t)row * DPH;
#pragma unroll
        for (int j = 0; j < 5; j++) {
            int c = lane + 32 * j;
            if (c < D) g_A16[base + c] = __float2half_rn(dv * acc[r][j]);
        }
        if (lane < DPH - D)            // zero pads cols 133..143
            g_A16[base + D + lane] = __float2half_rn(0.0f);
    }
}

// ------------------------------------------------------------------
// Warp-per-node CSR gather (fp16 messages, fp32 accum) + fused epilogue.
// acc = A[n] + sum_{src in in(n)} A[src];  v = relu(dinv[n]*acc + bias)*s + t
// do_pool==0: write v row (fp32) to Cout.  do_pool==1: red.v4 into g_P[batch[n]].
__global__ __launch_bounds__(256)
void gather_post_kernel(const __half* __restrict__ A, float* __restrict__ Cout,
                        const float* __restrict__ post, int do_pool,
                        const int* __restrict__ batch) {
    int gw = (blockIdx.x * blockDim.x + threadIdx.x) >> 5;
    if (gw >= N_NODES) return;
    int lane = threadIdx.x & 31;
    int n = gw;

    int lo = __ldg(&g_off[n]);
    int hi = __ldg(&g_off[n + 1]);

    float a[8];
#pragma unroll
    for (int i = 0; i < 8; i++) a[i] = 0.0f;

    // self term
    if (lane < 17) {
        const uint4 v = __ldg((const uint4*)(A + (size_t)n * DPH) + lane);
        const __half2* h = (const __half2*)&v;
#pragma unroll
        for (int q = 0; q < 4; q++) {
            float2 f = __half22float2(h[q]);
            a[2 * q] += f.x; a[2 * q + 1] += f.y;
        }
    }

    int e = lo;
    for (; e + 32 <= hi; e += 32) {
        int src = __ldg(&g_csr[e + lane]);
#pragma unroll 4
        for (int j = 0; j < 32; j++) {
            int sj = __shfl_sync(0xffffffffu, src, j);
            if (lane < 17) {
                const uint4 v = __ldg((const uint4*)(A + (size_t)sj * DPH) + lane);
                const __half2* h = (const __half2*)&v;
#pragma unroll
                for (int q = 0; q < 4; q++) {
                    float2 f = __half22float2(h[q]);
                    a[2 * q] += f.x; a[2 * q + 1] += f.y;
                }
            }
        }
    }
    for (; e < hi; e++) {
        int sj = __ldg(&g_csr[e]);
        if (lane < 17) {
            const uint4 v = __ldg((const uint4*)(A + (size_t)sj * DPH) + lane);
            const __half2* h = (const __half2*)&v;
#pragma unroll
            for (int q = 0; q < 4; q++) {
                float2 f = __half22float2(h[q]);
                a[2 * q] += f.x; a[2 * q + 1] += f.y;
            }
        }
    }

    if (lane >= 17) return;

    float dv = __ldg(&g_dinv[n]);
    const float* bb = post;
    const float* ss = post + DP;
    const float* tt = post + 2 * DP;

    int c0 = 8 * lane;                 // lane 0..16 -> cols 0..135
    float o[8];
#pragma unroll
    for (int i = 0; i < 8; i++) {
        float v = fmaf(dv, a[i], __ldg(&bb[c0 + i]));
        o[i] = fmaf(fmaxf(v, 0.0f), __ldg(&ss[c0 + i]), __ldg(&tt[c0 + i]));
    }

    if (!do_pool) {
        float4* Cn = (float4*)(Cout + (size_t)n * DP + c0);
        Cn[0] = make_float4(o[0], o[1], o[2], o[3]);
        Cn[1] = make_float4(o[4], o[5], o[6], o[7]);
    } else {
        int g = __ldg(&batch[n]);
        float* dst = g_P + (size_t)g * DP + c0;
        unsigned long long p0 = (unsigned long long)__cvta_generic_to_global(dst);
        asm volatile("red.global.add.v4.f32 [%0], {%1,%2,%3,%4};"
                     :: "l"(p0), "f"(o[0]), "f"(o[1]), "f"(o[2]), "f"(o[3]) : "memory");
        unsigned long long p1 = (unsigned long long)__cvta_generic_to_global(dst + 4);
        asm volatile("red.global.add.v4.f32 [%0], {%1,%2,%3,%4};"
                     :: "l"(p1), "f"(o[4]), "f"(o[5]), "f"(o[6]), "f"(o[7]) : "memory");
    }
}

// ------------------------------------------------------------------
__device__ __forceinline__ int lbound(const int* b, int n, int v) {
    int lo = 0, hi = n;
    while (lo < hi) { int m = (lo + hi) >> 1; if (b[m] < v) lo = m + 1; else hi = m; }
    return lo;
}

__global__ void cntg_kernel(const int* __restrict__ batch) {
    int g = blockIdx.x * blockDim.x + threadIdx.x;
    if (g < N_GRAPHS)
        g_cntg[g] = lbound(batch, N_NODES, g + 1) - lbound(batch, N_NODES, g);
}

__global__ void divide_kernel(float* __restrict__ out) {
    int idx = blockIdx.x * blockDim.x + threadIdx.x;
    if (idx >= N_GRAPHS * D) return;
    int g = idx / D;
    int c = idx - g * D;
    float cnt = (float)g_cntg[g];
    out[idx] = g_P[(size_t)g * DP + c] / fmaxf(cnt, 1.0f);
}

// ------------------------------------------------------------------
extern "C" void kernel_launch(void* const* d_in, const int* in_sizes, int n_in,
                              void* d_out, int out_size) {
    const float* x     = (const float*)d_in[0];
    const int*   ei    = (const int*)d_in[1];
    const int*   batch = (const int*)d_in[2];
    const float* W1  = (const float*)d_in[3];
    const float* b1  = (const float*)d_in[4];
    const float* W2  = (const float*)d_in[5];
    const float* b2  = (const float*)d_in[6];
    const float* g1  = (const float*)d_in[7];
    const float* be1 = (const float*)d_in[8];
    const float* rm1 = (const float*)d_in[9];
    const float* rv1 = (const float*)d_in[10];
    const float* g2  = (const float*)d_in[11];
    const float* be2 = (const float*)d_in[12];
    const float* rm2 = (const float*)d_in[13];
    const float* rv2 = (const float*)d_in[14];
    float* out = (float*)d_out;

    __half* pA;
    float *pC, *pP1, *pP2;
    cudaGetSymbolAddress((void**)&pA, g_A16);
    cudaGetSymbolAddress((void**)&pC, g_C);
    cudaGetSymbolAddress((void**)&pP1, g_post1);
    cudaGetSymbolAddress((void**)&pP2, g_post2);

    const int smem = (D * DP + 16 * GR * DP) * (int)sizeof(float);  // ~142 KB
    cudaFuncSetAttribute((const void*)gemm_scale_kernel,
                         cudaFuncAttributeMaxDynamicSharedMemorySize, smem);

    const int TB = 256;
    // ---- graph preprocessing (CSR + dinv) ----
    zero_cnt_kernel<<<(N_NODES + TB - 1) / TB, TB>>>();
    zero_pool_kernel<<<(N_GRAPHS * DP + TB - 1) / TB, TB>>>();
    count_deg_kernel<<<(N_EDGES + TB - 1) / TB, TB>>>(ei);
    dinv_kernel<<<(N_NODES + TB - 1) / TB, TB>>>();
    scan1_kernel<<<SCAN_NB, SCAN_B>>>();
    scan2_kernel<<<1, 32>>>();
    scan3_kernel<<<SCAN_NB, SCAN_B>>>();
    fill_csr_kernel<<<(N_EDGES + TB - 1) / TB, TB>>>(ei);
    prep_post_kernel<<<1, DP>>>(b1, g1, be1, rm1, rv1, pP1);
    prep_post_kernel<<<1, DP>>>(b2, g2, be2, rm2, rv2, pP2);

    const int gemm_blocks   = (N_NODES + 16 * GR - 1) / (16 * GR);
    const int gather_blocks = (N_NODES * 32 + TB - 1) / TB;   // warp per node

    // ---- layer 1 ----
    gemm_scale_kernel<<<gemm_blocks, GEMM_T, smem>>>(x, D, W1);
    gather_post_kernel<<<gather_blocks, TB>>>(pA, pC, pP1, 0, batch);

    // ---- layer 2 (+ fused pool accumulate) ----
    gemm_scale_kernel<<<gemm_blocks, GEMM_T, smem>>>(pC, DP, W2);
    gather_post_kernel<<<gather_blocks, TB>>>(pA, pC, pP2, 1, batch);

    // ---- per-graph mean ----
    cntg_kernel<<<(N_GRAPHS + TB - 1) / TB, TB>>>(batch);
    divide_kernel<<<(N_GRAPHS * D + TB - 1) / TB, TB>>>(out);
}